// round 1
// baseline (speedup 1.0000x reference)
#include <cuda_runtime.h>
#include <cuda_bf16.h>

// GraphSAGE 3-layer, mean aggregator, N=100000 nodes, E=1600000 edges, F=64.
// Strategy:
//   1. Build CSR by dst once per launch (histogram + single-block scan + scatter).
//   2. Per layer: (a) agg[n] = mean_{s in N(n)} h[s]   (warp per node, no atomics)
//                 (b) out[n] = leaky( h[n]@Ws^T + agg[n]@Wn^T + b )  (thread per node,
//                     weights transposed in smem, fp32 FFMA)
// h fits in L2 (25.6MB), so the 410MB/layer gather is L2-resident.

#define F 64
#define NMAX 100000
#define EMAX 1600000

__device__ int   g_counts[NMAX];
__device__ int   g_cursor[NMAX];
__device__ int   g_row_off[NMAX + 1];
__device__ int   g_csr[EMAX];
__device__ float g_bufA[(size_t)NMAX * F];
__device__ float g_bufB[(size_t)NMAX * F];
__device__ float g_agg [(size_t)NMAX * F];

// ---------------------------------------------------------------- CSR build

__global__ void k_zero_counts(int n) {
    int i = blockIdx.x * blockDim.x + threadIdx.x;
    if (i < n) g_counts[i] = 0;
}

__global__ void k_hist(const int* __restrict__ dst, int e) {
    int i = blockIdx.x * blockDim.x + threadIdx.x;
    if (i < e) atomicAdd(&g_counts[dst[i]], 1);
}

// Single-block exclusive scan over g_counts -> g_row_off (+ copy to g_cursor).
__global__ void k_scan(int n) {
    __shared__ int sh[1024];
    int t = threadIdx.x;
    int running = 0;
    for (int base = 0; base < n; base += 1024) {
        int i = base + t;
        int v = (i < n) ? g_counts[i] : 0;
        sh[t] = v;
        __syncthreads();
        // Hillis-Steele inclusive scan
        #pragma unroll
        for (int off = 1; off < 1024; off <<= 1) {
            int x = (t >= off) ? sh[t - off] : 0;
            __syncthreads();
            sh[t] += x;
            __syncthreads();
        }
        int incl = sh[t];
        int chunk_total = sh[1023];
        __syncthreads();
        if (i < n) {
            int excl = running + incl - v;
            g_row_off[i] = excl;
            g_cursor[i]  = excl;
        }
        running += chunk_total;
    }
    if (t == 0) g_row_off[n] = running;
}

__global__ void k_scatter(const int* __restrict__ src, const int* __restrict__ dst, int e) {
    int i = blockIdx.x * blockDim.x + threadIdx.x;
    if (i < e) {
        int p = atomicAdd(&g_cursor[dst[i]], 1);
        g_csr[p] = src[i];
    }
}

// ---------------------------------------------------------------- aggregate

// One warp per node. Lane l owns features [2l, 2l+1] (float2).
__global__ void k_aggregate(const float* __restrict__ h, int n) {
    int gtid = blockIdx.x * blockDim.x + threadIdx.x;
    int node = gtid >> 5;
    int lane = gtid & 31;
    if (node >= n) return;

    int beg = g_row_off[node];
    int end = g_row_off[node + 1];
    const float2* hp = (const float2*)h;

    float accx = 0.f, accy = 0.f;
    int e = beg;
    for (; e + 4 <= end; e += 4) {
        int s0 = g_csr[e + 0];
        int s1 = g_csr[e + 1];
        int s2 = g_csr[e + 2];
        int s3 = g_csr[e + 3];
        float2 v0 = hp[(size_t)s0 * 32 + lane];
        float2 v1 = hp[(size_t)s1 * 32 + lane];
        float2 v2 = hp[(size_t)s2 * 32 + lane];
        float2 v3 = hp[(size_t)s3 * 32 + lane];
        accx += (v0.x + v1.x) + (v2.x + v3.x);
        accy += (v0.y + v1.y) + (v2.y + v3.y);
    }
    for (; e < end; e++) {
        int s = g_csr[e];
        float2 v = hp[(size_t)s * 32 + lane];
        accx += v.x;
        accy += v.y;
    }
    int deg = end - beg;
    float inv = 1.f / (float)(deg > 0 ? deg : 1);
    float2 r;
    r.x = accx * inv;
    r.y = accy * inv;
    ((float2*)g_agg)[(size_t)node * 32 + lane] = r;
}

// ---------------------------------------------------------------- transform

// acc[j] += sum_k row[k] * Wt[k*64 + j]   (Wt = W transposed, in smem; all lanes
// broadcast-read the same Wt element -> conflict-free)
__device__ __forceinline__ void mac_row(const float* __restrict__ row,
                                        const float* __restrict__ Wt,
                                        float acc[F]) {
    for (int k0 = 0; k0 < F; k0 += 4) {          // NOT unrolled (keep I$ small)
        float4 hv = ((const float4*)row)[k0 >> 2];
        float hk[4] = {hv.x, hv.y, hv.z, hv.w};
        #pragma unroll
        for (int kk = 0; kk < 4; kk++) {
            const float4* wr = (const float4*)&Wt[(k0 + kk) * F];
            float h = hk[kk];
            #pragma unroll
            for (int j = 0; j < 16; j++) {
                float4 w = wr[j];
                acc[4 * j + 0] += h * w.x;
                acc[4 * j + 1] += h * w.y;
                acc[4 * j + 2] += h * w.z;
                acc[4 * j + 3] += h * w.w;
            }
        }
    }
}

__global__ void k_transform(const float* __restrict__ h,
                            const float* __restrict__ agg,
                            const float* __restrict__ Ws,
                            const float* __restrict__ Wn,
                            const float* __restrict__ b,
                            float* __restrict__ out,
                            int n, int leaky) {
    __shared__ float Wts[F * F];
    __shared__ float Wtn[F * F];
    __shared__ float sb[F];

    int t = threadIdx.x;
    for (int i = t; i < F * F; i += blockDim.x) {
        int j = i >> 6, k = i & 63;          // W[j][k] -> Wt[k][j]
        Wts[k * F + j] = Ws[i];
        Wtn[k * F + j] = Wn[i];
    }
    if (t < F) sb[t] = b[t];
    __syncthreads();

    int node = blockIdx.x * blockDim.x + t;
    if (node >= n) return;

    float acc[F];
    #pragma unroll
    for (int j = 0; j < F; j++) acc[j] = sb[j];

    mac_row(h   + (size_t)node * F, Wts, acc);
    mac_row(agg + (size_t)node * F, Wtn, acc);

    float4* o = (float4*)(out + (size_t)node * F);
    if (leaky) {
        #pragma unroll
        for (int j4 = 0; j4 < 16; j4++) {
            float4 v;
            float a0 = acc[4 * j4 + 0], a1 = acc[4 * j4 + 1];
            float a2 = acc[4 * j4 + 2], a3 = acc[4 * j4 + 3];
            v.x = a0 >= 0.f ? a0 : 0.01f * a0;
            v.y = a1 >= 0.f ? a1 : 0.01f * a1;
            v.z = a2 >= 0.f ? a2 : 0.01f * a2;
            v.w = a3 >= 0.f ? a3 : 0.01f * a3;
            o[j4] = v;
        }
    } else {
        #pragma unroll
        for (int j4 = 0; j4 < 16; j4++) {
            float4 v;
            v.x = acc[4 * j4 + 0];
            v.y = acc[4 * j4 + 1];
            v.z = acc[4 * j4 + 2];
            v.w = acc[4 * j4 + 3];
            o[j4] = v;
        }
    }
}

// ---------------------------------------------------------------- launch

extern "C" void kernel_launch(void* const* d_in, const int* in_sizes, int n_in,
                              void* d_out, int out_size) {
    const float* in_feat = (const float*)d_in[0];
    const int*   src     = (const int*)d_in[1];
    const int*   dst     = (const int*)d_in[2];
    const float* w_self1 = (const float*)d_in[3];
    const float* w_nei1  = (const float*)d_in[4];
    const float* b1      = (const float*)d_in[5];
    const float* w_self2 = (const float*)d_in[6];
    const float* w_nei2  = (const float*)d_in[7];
    const float* b2      = (const float*)d_in[8];
    const float* w_self3 = (const float*)d_in[9];
    const float* w_nei3  = (const float*)d_in[10];
    const float* b3      = (const float*)d_in[11];
    float* out = (float*)d_out;

    int n = in_sizes[0] / F;     // 100000
    int e = in_sizes[1];         // 1600000

    // device-symbol pointers (host-side address query; not a stream op)
    float *bufA, *bufB, *agg;
    cudaGetSymbolAddress((void**)&bufA, g_bufA);
    cudaGetSymbolAddress((void**)&bufB, g_bufB);
    cudaGetSymbolAddress((void**)&agg,  g_agg);

    // ---- CSR build (once per launch) ----
    k_zero_counts<<<(n + 255) / 256, 256>>>(n);
    k_hist<<<(e + 255) / 256, 256>>>(dst, e);
    k_scan<<<1, 1024>>>(n);
    k_scatter<<<(e + 255) / 256, 256>>>(src, dst, e);

    int agg_grid = (n * 32 + 255) / 256;   // warp per node, 8 warps/block
    int tr_grid  = (n + 255) / 256;

    // ---- layer 1 ----
    k_aggregate<<<agg_grid, 256>>>(in_feat, n);
    k_transform<<<tr_grid, 256>>>(in_feat, agg, w_self1, w_nei1, b1, bufA, n, 1);
    // ---- layer 2 ----
    k_aggregate<<<agg_grid, 256>>>(bufA, n);
    k_transform<<<tr_grid, 256>>>(bufA, agg, w_self2, w_nei2, b2, bufB, n, 1);
    // ---- layer 3 ----
    k_aggregate<<<agg_grid, 256>>>(bufB, n);
    k_transform<<<tr_grid, 256>>>(bufB, agg, w_self3, w_nei3, b3, out, n, 0);
}

// round 2
// speedup vs baseline: 1.3284x; 1.3284x over previous
#include <cuda_runtime.h>
#include <cuda_bf16.h>

// GraphSAGE 3-layer, mean aggregator, N=100000, E=1600000, F=64.
// R2: multi-block scan (was single-block, ~80us on one SM) + packed f32x2 FMA
//     in the transform (halves FMA-pipe issue count).

#define F 64
#define NMAX 100000
#define EMAX 1600000
#define SCAN_BS 512

__device__ int   g_counts[NMAX];
__device__ int   g_cursor[NMAX];
__device__ int   g_row_off[NMAX + 1];
__device__ int   g_partials[256];
__device__ int   g_poff[256];
__device__ int   g_total;
__device__ int   g_csr[EMAX];
__device__ __align__(16) float g_bufA[(size_t)NMAX * F];
__device__ __align__(16) float g_bufB[(size_t)NMAX * F];
__device__ __align__(16) float g_agg [(size_t)NMAX * F];

// ---------------------------------------------------------------- CSR build

__global__ void k_hist(const int* __restrict__ dst, int e) {
    int i = blockIdx.x * blockDim.x + threadIdx.x;
    if (i < e) atomicAdd(&g_counts[dst[i]], 1);
}

// Pass 1: per-block exclusive scan of counts (512/block), block totals out.
__global__ void k_scan_blocks(int n) {
    int i = blockIdx.x * SCAN_BS + threadIdx.x;
    int v = (i < n) ? g_counts[i] : 0;
    int lane = threadIdx.x & 31, wid = threadIdx.x >> 5;

    int incl = v;
    #pragma unroll
    for (int o = 1; o < 32; o <<= 1) {
        int x = __shfl_up_sync(0xffffffffu, incl, o);
        if (lane >= o) incl += x;
    }
    __shared__ int ws[16];
    if (lane == 31) ws[wid] = incl;
    __syncthreads();
    if (wid == 0) {
        int s = (lane < 16) ? ws[lane] : 0;
        #pragma unroll
        for (int o = 1; o < 16; o <<= 1) {
            int x = __shfl_up_sync(0xffffffffu, s, o);
            if (lane >= o) s += x;
        }
        if (lane < 16) ws[lane] = s;      // inclusive warp-sum scan
    }
    __syncthreads();
    int excl = incl - v + (wid ? ws[wid - 1] : 0);
    if (i < n) g_cursor[i] = excl;        // within-block exclusive (temp)
    if (threadIdx.x == SCAN_BS - 1) g_partials[blockIdx.x] = ws[15];
}

// Pass 2: scan the (<=256) block totals in one tiny block.
__global__ void k_scan_partials(int nb) {
    int t = threadIdx.x;                  // 256 threads = 8 warps
    int lane = t & 31, wid = t >> 5;
    int v = (t < nb) ? g_partials[t] : 0;
    int incl = v;
    #pragma unroll
    for (int o = 1; o < 32; o <<= 1) {
        int x = __shfl_up_sync(0xffffffffu, incl, o);
        if (lane >= o) incl += x;
    }
    __shared__ int ws[8];
    if (lane == 31) ws[wid] = incl;
    __syncthreads();
    if (wid == 0) {
        int s = (lane < 8) ? ws[lane] : 0;
        #pragma unroll
        for (int o = 1; o < 8; o <<= 1) {
            int x = __shfl_up_sync(0xffffffffu, s, o);
            if (lane >= o) s += x;
        }
        if (lane < 8) ws[lane] = s;
    }
    __syncthreads();
    incl += (wid ? ws[wid - 1] : 0);
    g_poff[t] = incl - v;                 // exclusive prefix of partials
    if (t == 255) g_total = incl;         // grand total (v=0 past nb)
}

// Pass 3: add block offsets, emit row_off + cursor.
__global__ void k_scan_finalize(int n) {
    int i = blockIdx.x * SCAN_BS + threadIdx.x;
    if (i < n) {
        int off = g_cursor[i] + g_poff[i >> 9];   // 512 = 1<<9
        g_row_off[i] = off;
        g_cursor[i]  = off;
        if (i == n - 1) g_row_off[n] = g_total;
    }
}

__global__ void k_scatter(const int* __restrict__ src, const int* __restrict__ dst, int e) {
    int i = blockIdx.x * blockDim.x + threadIdx.x;
    if (i < e) {
        int p = atomicAdd(&g_cursor[dst[i]], 1);
        g_csr[p] = src[i];
    }
}

// ---------------------------------------------------------------- aggregate

// One warp per node. Lane l owns features [2l, 2l+1] (float2).
__global__ void k_aggregate(const float* __restrict__ h, int n) {
    int gtid = blockIdx.x * blockDim.x + threadIdx.x;
    int node = gtid >> 5;
    int lane = gtid & 31;
    if (node >= n) return;

    int beg = g_row_off[node];
    int end = g_row_off[node + 1];
    const float2* hp = (const float2*)h;

    float accx = 0.f, accy = 0.f;
    int e = beg;
    for (; e + 4 <= end; e += 4) {
        int s0 = g_csr[e + 0];
        int s1 = g_csr[e + 1];
        int s2 = g_csr[e + 2];
        int s3 = g_csr[e + 3];
        float2 v0 = hp[(size_t)s0 * 32 + lane];
        float2 v1 = hp[(size_t)s1 * 32 + lane];
        float2 v2 = hp[(size_t)s2 * 32 + lane];
        float2 v3 = hp[(size_t)s3 * 32 + lane];
        accx += (v0.x + v1.x) + (v2.x + v3.x);
        accy += (v0.y + v1.y) + (v2.y + v3.y);
    }
    for (; e < end; e++) {
        int s = g_csr[e];
        float2 v = hp[(size_t)s * 32 + lane];
        accx += v.x;
        accy += v.y;
    }
    int deg = end - beg;
    float inv = 1.f / (float)(deg > 0 ? deg : 1);
    float2 r;
    r.x = accx * inv;
    r.y = accy * inv;
    ((float2*)g_agg)[(size_t)node * 32 + lane] = r;
}

// ---------------------------------------------------------------- transform

// Packed dual-FMA: acc(2 floats) += {h,h} * {w0,w1}   (Blackwell f32x2 pipe)
__device__ __forceinline__ void ffma2(unsigned long long& acc,
                                      unsigned long long a,
                                      unsigned long long b) {
    asm("fma.rn.f32x2 %0, %1, %2, %0;" : "+l"(acc) : "l"(a), "l"(b));
}

__device__ __forceinline__ unsigned long long pack2(float h) {
    unsigned long long r;
    asm("mov.b64 %0, {%1, %1};" : "=l"(r) : "f"(h));
    return r;
}

__device__ __forceinline__ void unpack2(unsigned long long p, float& lo, float& hi) {
    asm("mov.b64 {%0, %1}, %2;" : "=f"(lo), "=f"(hi) : "l"(p));
}

// acc[j] pair += row[k] * Wt[k][2j..2j+1], Wt transposed in smem (broadcast reads)
__device__ __forceinline__ void mac_row2(const float* __restrict__ row,
                                         const float* __restrict__ Wt,
                                         unsigned long long acc[F / 2]) {
    for (int k0 = 0; k0 < F; k0 += 4) {          // NOT unrolled (keep I$ small)
        float4 hv = ((const float4*)row)[k0 >> 2];
        float hk[4] = {hv.x, hv.y, hv.z, hv.w};
        #pragma unroll
        for (int kk = 0; kk < 4; kk++) {
            unsigned long long hh = pack2(hk[kk]);
            const ulonglong2* wr = (const ulonglong2*)&Wt[(k0 + kk) * F];
            #pragma unroll
            for (int j = 0; j < 16; j++) {
                ulonglong2 w = wr[j];
                ffma2(acc[2 * j + 0], hh, w.x);
                ffma2(acc[2 * j + 1], hh, w.y);
            }
        }
    }
}

__global__ void k_transform(const float* __restrict__ h,
                            const float* __restrict__ agg,
                            const float* __restrict__ Ws,
                            const float* __restrict__ Wn,
                            const float* __restrict__ b,
                            float* __restrict__ out,
                            int n, int leaky) {
    __shared__ __align__(16) float Wts[F * F];
    __shared__ __align__(16) float Wtn[F * F];
    __shared__ __align__(16) float sb[F];

    int t = threadIdx.x;
    for (int i = t; i < F * F; i += blockDim.x) {
        int j = i >> 6, k = i & 63;              // W[j][k] -> Wt[k][j]
        Wts[k * F + j] = Ws[i];
        Wtn[k * F + j] = Wn[i];
    }
    if (t < F) sb[t] = b[t];
    __syncthreads();

    int node = blockIdx.x * blockDim.x + t;
    if (node >= n) return;

    unsigned long long acc[F / 2];
    const unsigned long long* bp = (const unsigned long long*)sb;
    #pragma unroll
    for (int j = 0; j < F / 2; j++) acc[j] = bp[j];

    mac_row2(h   + (size_t)node * F, Wts, acc);
    mac_row2(agg + (size_t)node * F, Wtn, acc);

    float4* o = (float4*)(out + (size_t)node * F);
    #pragma unroll
    for (int j4 = 0; j4 < 16; j4++) {
        float a0, a1, a2, a3;
        unpack2(acc[2 * j4 + 0], a0, a1);
        unpack2(acc[2 * j4 + 1], a2, a3);
        float4 v;
        if (leaky) {
            v.x = a0 >= 0.f ? a0 : 0.01f * a0;
            v.y = a1 >= 0.f ? a1 : 0.01f * a1;
            v.z = a2 >= 0.f ? a2 : 0.01f * a2;
            v.w = a3 >= 0.f ? a3 : 0.01f * a3;
        } else {
            v.x = a0; v.y = a1; v.z = a2; v.w = a3;
        }
        o[j4] = v;
    }
}

// ---------------------------------------------------------------- launch

extern "C" void kernel_launch(void* const* d_in, const int* in_sizes, int n_in,
                              void* d_out, int out_size) {
    const float* in_feat = (const float*)d_in[0];
    const int*   src     = (const int*)d_in[1];
    const int*   dst     = (const int*)d_in[2];
    const float* w_self1 = (const float*)d_in[3];
    const float* w_nei1  = (const float*)d_in[4];
    const float* b1      = (const float*)d_in[5];
    const float* w_self2 = (const float*)d_in[6];
    const float* w_nei2  = (const float*)d_in[7];
    const float* b2      = (const float*)d_in[8];
    const float* w_self3 = (const float*)d_in[9];
    const float* w_nei3  = (const float*)d_in[10];
    const float* b3      = (const float*)d_in[11];
    float* out = (float*)d_out;

    int n = in_sizes[0] / F;     // 100000
    int e = in_sizes[1];         // 1600000
    int nscan = (n + SCAN_BS - 1) / SCAN_BS;   // 196

    float *bufA, *bufB, *agg;
    int* counts;
    cudaGetSymbolAddress((void**)&bufA, g_bufA);
    cudaGetSymbolAddress((void**)&bufB, g_bufB);
    cudaGetSymbolAddress((void**)&agg,  g_agg);
    cudaGetSymbolAddress((void**)&counts, g_counts);

    // ---- CSR build (once per launch) ----
    cudaMemsetAsync(counts, 0, (size_t)n * sizeof(int));
    k_hist<<<(e + 255) / 256, 256>>>(dst, e);
    k_scan_blocks<<<nscan, SCAN_BS>>>(n);
    k_scan_partials<<<1, 256>>>(nscan);
    k_scan_finalize<<<nscan, SCAN_BS>>>(n);
    k_scatter<<<(e + 255) / 256, 256>>>(src, dst, e);

    int agg_grid = (n * 32 + 255) / 256;   // warp per node
    int tr_grid  = (n + 255) / 256;

    // ---- layer 1 ----
    k_aggregate<<<agg_grid, 256>>>(in_feat, n);
    k_transform<<<tr_grid, 256>>>(in_feat, agg, w_self1, w_nei1, b1, bufA, n, 1);
    // ---- layer 2 ----
    k_aggregate<<<agg_grid, 256>>>(bufA, n);
    k_transform<<<tr_grid, 256>>>(bufA, agg, w_self2, w_nei2, b2, bufB, n, 1);
    // ---- layer 3 ----
    k_aggregate<<<agg_grid, 256>>>(bufB, n);
    k_transform<<<tr_grid, 256>>>(bufB, agg, w_self3, w_nei3, b3, out, n, 0);
}